// round 5
// baseline (speedup 1.0000x reference)
#include <cuda_runtime.h>

#define EDIM    4096
#define BATCH   8
#define HEADS   32
#define DHEAD   128
#define TPREV   2047
#define TTOT    2048
#define NSPLIT  8
#define TOK_PER_BLOCK 256   // 8 warps * 32 tokens

// ---------------- scratch (device globals, no allocation) ----------------
__device__ float g_q[BATCH * EDIM];
__device__ float g_k[BATCH * EDIM];
__device__ float g_v[BATCH * EDIM];
__device__ float g_attn[BATCH * EDIM];
__device__ float g_pm[BATCH * HEADS * NSPLIT];
__device__ float g_pl[BATCH * HEADS * NSPLIT];
__device__ float g_pacc[BATCH * HEADS * NSPLIT * DHEAD];

// ---------------- GEMV body: Y[b][row] = sum_i X[b][i]*W[row][i]+bias ----
// block = 256 threads = 8 warps; warp w handles batch w for row blockIdx.x.
// The 16KB W row is read by 8 warps; L1 dedups to one DRAM stream.
__device__ __forceinline__ void gemv_row(const float* __restrict__ X,
                                         const float* __restrict__ W,
                                         const float* __restrict__ bias,
                                         float* __restrict__ Y) {
    const int row  = blockIdx.x;
    const int warp = threadIdx.x >> 5;   // batch 0..7
    const int lane = threadIdx.x & 31;

    const float* wrow = W + (size_t)row * EDIM;
    const float* xb   = X + warp * EDIM;

    float sum = 0.f;
#pragma unroll
    for (int k = 0; k < EDIM / 128; ++k) {           // 32 iterations
        const int i = (k * 32 + lane) * 4;
        const float4 w4 = *(const float4*)&wrow[i];
        const float4 x4 = *(const float4*)&xb[i];
        sum += w4.x * x4.x + w4.y * x4.y + w4.z * x4.z + w4.w * x4.w;
    }
#pragma unroll
    for (int s = 16; s > 0; s >>= 1)
        sum += __shfl_xor_sync(0xffffffffu, sum, s);
    if (lane == 0)
        Y[warp * EDIM + row] = sum + bias[row];
}

// QKV fused over blockIdx.y; destinations are device globals referenced
// from DEVICE code only.
__global__ void qkv_gemv(const float* __restrict__ x,
                         const float* __restrict__ Wq, const float* __restrict__ bq,
                         const float* __restrict__ Wk, const float* __restrict__ bk,
                         const float* __restrict__ Wv, const float* __restrict__ bv) {
    const int p = blockIdx.y;
    const float* W    = (p == 0) ? Wq : (p == 1) ? Wk : Wv;
    const float* bias = (p == 0) ? bq : (p == 1) ? bk : bv;
    float* Y          = (p == 0) ? g_q : (p == 1) ? g_k : g_v;
    gemv_row(x, W, bias, Y);
}

// Output projection: reads g_attn inside device code.
__global__ void out_gemv(const float* __restrict__ Wo,
                         const float* __restrict__ bo,
                         float* __restrict__ out) {
    gemv_row(g_attn, Wo, bo, out);
}

// ---------------- fused cache-copy + flash attention ----------------------
// grid: (NSPLIT, HEADS, BATCH), block 256 (8 warps x 32 tokens each)
// NOTE: the reference slices q AFTER transposing to (b, h, s, d), so
// q[:, -1:] selects the LAST HEAD (h=31), broadcast to all heads.
__global__ void attn_kernel(const float* __restrict__ kc,
                            const float* __restrict__ vc,
                            float* __restrict__ kout,
                            float* __restrict__ vout) {
    const int split = blockIdx.x;
    const int h = blockIdx.y;
    const int b = blockIdx.z;
    const int warp = threadIdx.x >> 5;
    const int lane = threadIdx.x & 31;
    const int bh = b * HEADS + h;

    // q from head 31 for ALL heads (reference broadcast semantics)
    const float4 q4 = *(const float4*)&g_q[b * EDIM + (HEADS - 1) * DHEAD + lane * 4];
    const float scale = 0.08838834764831845f;  // 1/sqrt(128)

    float m = -1e30f, l = 0.f;
    float4 acc = make_float4(0.f, 0.f, 0.f, 0.f);

    const int tok0 = split * TOK_PER_BLOCK + warp * 32;

#pragma unroll 4
    for (int j = 0; j < 32; ++j) {
        const int tok = tok0 + j;
        const float* kp;
        const float* vp;
        if (tok < TPREV) {
            const size_t off = ((size_t)bh * TPREV + tok) * DHEAD;
            kp = kc + off;
            vp = vc + off;
        } else {
            kp = g_k + b * EDIM + h * DHEAD;
            vp = g_v + b * EDIM + h * DHEAD;
        }
        const float4 k4 = *(const float4*)&kp[lane * 4];
        const float4 v4 = *(const float4*)&vp[lane * 4];

        // cache copy rides the same read
        const size_t oo = ((size_t)bh * TTOT + tok) * DHEAD + lane * 4;
        *(float4*)&kout[oo] = k4;
        *(float4*)&vout[oo] = v4;

        float s = q4.x * k4.x + q4.y * k4.y + q4.z * k4.z + q4.w * k4.w;
#pragma unroll
        for (int sh = 16; sh > 0; sh >>= 1)
            s += __shfl_xor_sync(0xffffffffu, s, sh);
        s *= scale;

        const float mn = fmaxf(m, s);
        const float sc = __expf(m - mn);
        const float p  = __expf(s - mn);
        l = l * sc + p;
        acc.x = acc.x * sc + p * v4.x;
        acc.y = acc.y * sc + p * v4.y;
        acc.z = acc.z * sc + p * v4.z;
        acc.w = acc.w * sc + p * v4.w;
        m = mn;
    }

    // combine the 8 warps of this block
    __shared__ float sm_m[8], sm_l[8];
    __shared__ __align__(16) float sm_acc[8][DHEAD];
    if (lane == 0) { sm_m[warp] = m; sm_l[warp] = l; }
    *(float4*)&sm_acc[warp][lane * 4] = acc;
    __syncthreads();

    if (threadIdx.x < DHEAD) {
        const int d = threadIdx.x;
        float M = -1e30f;
#pragma unroll
        for (int w = 0; w < 8; ++w) M = fmaxf(M, sm_m[w]);
        float L = 0.f, A = 0.f;
#pragma unroll
        for (int w = 0; w < 8; ++w) {
            const float e = __expf(sm_m[w] - M);
            L += sm_l[w] * e;
            A += sm_acc[w][d] * e;
        }
        const int idx = bh * NSPLIT + split;
        g_pacc[idx * DHEAD + d] = A;
        if (d == 0) { g_pm[idx] = M; g_pl[idx] = L; }
    }
}

// merge NSPLIT partial softmaxes per (b,h)
__global__ void combine_kernel() {
    const int bh = blockIdx.x;   // 0..255
    const int d = threadIdx.x;   // 0..127
    float M = -1e30f;
#pragma unroll
    for (int s = 0; s < NSPLIT; ++s)
        M = fmaxf(M, g_pm[bh * NSPLIT + s]);
    float L = 0.f, A = 0.f;
#pragma unroll
    for (int s = 0; s < NSPLIT; ++s) {
        const float e = __expf(g_pm[bh * NSPLIT + s] - M);
        L += g_pl[bh * NSPLIT + s] * e;
        A += g_pacc[(bh * NSPLIT + s) * DHEAD + d] * e;
    }
    const int b = bh / HEADS;
    const int h = bh % HEADS;
    g_attn[b * EDIM + h * DHEAD + d] = A / L;
}

// ---------------- launch ---------------------------------------------------
extern "C" void kernel_launch(void* const* d_in, const int* in_sizes, int n_in,
                              void* d_out, int out_size) {
    // Defensive input mapping based on element counts.
    const float *x, *kc, *vc, *Wq, *bq, *Wk, *bk, *Wv, *bv, *Wo, *bo;
    if (in_sizes[0] == BATCH * EDIM) {
        // signature/dict order: x, kc, vc, Wq, bq, Wk, bk, Wv, bv, Wo, bo
        x  = (const float*)d_in[0];
        kc = (const float*)d_in[1];
        vc = (const float*)d_in[2];
        Wq = (const float*)d_in[3];
        bq = (const float*)d_in[4];
        Wk = (const float*)d_in[5];
        bk = (const float*)d_in[6];
        Wv = (const float*)d_in[7];
        bv = (const float*)d_in[8];
        Wo = (const float*)d_in[9];
        bo = (const float*)d_in[10];
    } else {
        // alphabetical order: Wk, Wo, Wq, Wv, bk, bo, bq, bv, kc, vc, x
        Wk = (const float*)d_in[0];
        Wo = (const float*)d_in[1];
        Wq = (const float*)d_in[2];
        Wv = (const float*)d_in[3];
        bk = (const float*)d_in[4];
        bo = (const float*)d_in[5];
        bq = (const float*)d_in[6];
        bv = (const float*)d_in[7];
        kc = (const float*)d_in[8];
        vc = (const float*)d_in[9];
        x  = (const float*)d_in[10];
    }

    float* out  = (float*)d_out;                                   // [8,1,4096]
    float* kout = out + (size_t)BATCH * EDIM;                      // [8,32,2048,128]
    float* vout = kout + (size_t)BATCH * HEADS * TTOT * DHEAD;     // [8,32,2048,128]

    qkv_gemv<<<dim3(EDIM, 3), 256>>>(x, Wq, bq, Wk, bk, Wv, bv);
    attn_kernel<<<dim3(NSPLIT, HEADS, BATCH), 256>>>(kc, vc, kout, vout);
    combine_kernel<<<BATCH * HEADS, DHEAD>>>();
    out_gemv<<<EDIM, 256>>>(Wo, bo, out);
}

// round 6
// speedup vs baseline: 1.2665x; 1.2665x over previous
#include <cuda_runtime.h>

#define EDIM    4096
#define BATCH   8
#define HEADS   32
#define DHEAD   128
#define TPREV   2047
#define TTOT    2048
#define NSPLIT  8
#define TOK_PER_BLOCK 256   // 8 warps * 32 tokens

// ---------------- scratch (device globals, no allocation) ----------------
__device__ float g_q[BATCH * EDIM];
__device__ float g_k[BATCH * EDIM];
__device__ float g_v[BATCH * EDIM];
__device__ float g_attn[BATCH * EDIM];
__device__ float g_pm[BATCH * HEADS * NSPLIT];
__device__ float g_pl[BATCH * HEADS * NSPLIT];
__device__ float g_pacc[BATCH * HEADS * NSPLIT * DHEAD];

// ---------------- row-blocked GEMV ----------------------------------------
// Y[b][row] = sum_i X[b][i] * W[row][i] + bias[row]
// Block: 256 threads = 8 warps. Each warp owns 4 DISTINCT W rows (no L1
// read duplication); x staged through 32KB smem chunks; 32 accs in regs.
__device__ __forceinline__ void gemv_body(const float* __restrict__ X,
                                          const float* __restrict__ W,
                                          const float* __restrict__ bias,
                                          float* __restrict__ Y,
                                          float* xs /* [8*1024] */) {
    const int warp = threadIdx.x >> 5;
    const int lane = threadIdx.x & 31;
    const int row0 = blockIdx.x * 32 + warp * 4;

    float acc[4][8];
#pragma unroll
    for (int r = 0; r < 4; ++r)
#pragma unroll
        for (int b = 0; b < 8; ++b) acc[r][b] = 0.f;

    for (int c = 0; c < 4; ++c) {
        const int base = c * 1024;
        __syncthreads();
        // stage x chunk: 8 batches x 1024 floats = 2048 float4
#pragma unroll
        for (int t = threadIdx.x; t < 2048; t += 256) {
            const int f = t * 4;
            const int b = f >> 10;
            const int i = f & 1023;
            *(float4*)&xs[b * 1024 + i] = *(const float4*)&X[b * EDIM + base + i];
        }
        __syncthreads();
#pragma unroll
        for (int stp = 0; stp < 8; ++stp) {
            const int i0 = stp * 128 + lane * 4;
            float4 w4[4];
#pragma unroll
            for (int r = 0; r < 4; ++r)
                w4[r] = *(const float4*)&W[(size_t)(row0 + r) * EDIM + base + i0];
#pragma unroll
            for (int b = 0; b < 8; ++b) {
                const float4 x4 = *(const float4*)&xs[b * 1024 + i0];
#pragma unroll
                for (int r = 0; r < 4; ++r) {
                    acc[r][b] += w4[r].x * x4.x;
                    acc[r][b] += w4[r].y * x4.y;
                    acc[r][b] += w4[r].z * x4.z;
                    acc[r][b] += w4[r].w * x4.w;
                }
            }
        }
    }

    // warp-reduce all 32 accumulators; lane = r*8+b picks its result
#pragma unroll
    for (int r = 0; r < 4; ++r)
#pragma unroll
        for (int b = 0; b < 8; ++b) {
            float v = acc[r][b];
#pragma unroll
            for (int s = 16; s > 0; s >>= 1)
                v += __shfl_xor_sync(0xffffffffu, v, s);
            acc[r][b] = v;
        }
    const int r = lane >> 3;
    const int b = lane & 7;
    Y[b * EDIM + row0 + r] = acc[r][b] + bias[row0 + r];
}

// QKV fused over blockIdx.y; destinations are device globals referenced
// from DEVICE code only.
__global__ void qkv_gemv(const float* __restrict__ x,
                         const float* __restrict__ Wq, const float* __restrict__ bq,
                         const float* __restrict__ Wk, const float* __restrict__ bk,
                         const float* __restrict__ Wv, const float* __restrict__ bv) {
    __shared__ float xs[8 * 1024];
    const int p = blockIdx.y;
    const float* W    = (p == 0) ? Wq : (p == 1) ? Wk : Wv;
    const float* bias = (p == 0) ? bq : (p == 1) ? bk : bv;
    float* Y          = (p == 0) ? g_q : (p == 1) ? g_k : g_v;
    gemv_body(x, W, bias, Y, xs);
}

// Output projection: reads g_attn inside device code.
__global__ void out_gemv(const float* __restrict__ Wo,
                         const float* __restrict__ bo,
                         float* __restrict__ out) {
    __shared__ float xs[8 * 1024];
    gemv_body(g_attn, Wo, bo, out, xs);
}

// ---------------- fused cache-copy + flash attention ----------------------
// grid: (NSPLIT, HEADS, BATCH), block 256 (8 warps x 32 tokens each)
// NOTE: the reference slices q AFTER transposing to (b, h, s, d), so
// q[:, -1:] selects the LAST HEAD (h=31), broadcast to all heads.
__global__ void attn_kernel(const float* __restrict__ kc,
                            const float* __restrict__ vc,
                            float* __restrict__ kout,
                            float* __restrict__ vout) {
    const int split = blockIdx.x;
    const int h = blockIdx.y;
    const int b = blockIdx.z;
    const int warp = threadIdx.x >> 5;
    const int lane = threadIdx.x & 31;
    const int bh = b * HEADS + h;

    // q from head 31 for ALL heads (reference broadcast semantics)
    const float4 q4 = *(const float4*)&g_q[b * EDIM + (HEADS - 1) * DHEAD + lane * 4];
    const float scale = 0.08838834764831845f;  // 1/sqrt(128)

    float m = -1e30f, l = 0.f;
    float4 acc = make_float4(0.f, 0.f, 0.f, 0.f);

    const int tok0 = split * TOK_PER_BLOCK + warp * 32;

#pragma unroll 4
    for (int j = 0; j < 32; ++j) {
        const int tok = tok0 + j;
        const float* kp;
        const float* vp;
        if (tok < TPREV) {
            const size_t off = ((size_t)bh * TPREV + tok) * DHEAD;
            kp = kc + off;
            vp = vc + off;
        } else {
            kp = g_k + b * EDIM + h * DHEAD;
            vp = g_v + b * EDIM + h * DHEAD;
        }
        const float4 k4 = *(const float4*)&kp[lane * 4];
        const float4 v4 = *(const float4*)&vp[lane * 4];

        // cache copy rides the same read
        const size_t oo = ((size_t)bh * TTOT + tok) * DHEAD + lane * 4;
        *(float4*)&kout[oo] = k4;
        *(float4*)&vout[oo] = v4;

        float s = q4.x * k4.x + q4.y * k4.y + q4.z * k4.z + q4.w * k4.w;
#pragma unroll
        for (int sh = 16; sh > 0; sh >>= 1)
            s += __shfl_xor_sync(0xffffffffu, s, sh);
        s *= scale;

        const float mn = fmaxf(m, s);
        const float sc = __expf(m - mn);
        const float p  = __expf(s - mn);
        l = l * sc + p;
        acc.x = acc.x * sc + p * v4.x;
        acc.y = acc.y * sc + p * v4.y;
        acc.z = acc.z * sc + p * v4.z;
        acc.w = acc.w * sc + p * v4.w;
        m = mn;
    }

    // combine the 8 warps of this block
    __shared__ float sm_m[8], sm_l[8];
    __shared__ __align__(16) float sm_acc[8][DHEAD];
    if (lane == 0) { sm_m[warp] = m; sm_l[warp] = l; }
    *(float4*)&sm_acc[warp][lane * 4] = acc;
    __syncthreads();

    if (threadIdx.x < DHEAD) {
        const int d = threadIdx.x;
        float M = -1e30f;
#pragma unroll
        for (int w = 0; w < 8; ++w) M = fmaxf(M, sm_m[w]);
        float L = 0.f, A = 0.f;
#pragma unroll
        for (int w = 0; w < 8; ++w) {
            const float e = __expf(sm_m[w] - M);
            L += sm_l[w] * e;
            A += sm_acc[w][d] * e;
        }
        const int idx = bh * NSPLIT + split;
        g_pacc[idx * DHEAD + d] = A;
        if (d == 0) { g_pm[idx] = M; g_pl[idx] = L; }
    }
}

// merge NSPLIT partial softmaxes per (b,h)
__global__ void combine_kernel() {
    const int bh = blockIdx.x;   // 0..255
    const int d = threadIdx.x;   // 0..127
    float M = -1e30f;
#pragma unroll
    for (int s = 0; s < NSPLIT; ++s)
        M = fmaxf(M, g_pm[bh * NSPLIT + s]);
    float L = 0.f, A = 0.f;
#pragma unroll
    for (int s = 0; s < NSPLIT; ++s) {
        const float e = __expf(g_pm[bh * NSPLIT + s] - M);
        L += g_pl[bh * NSPLIT + s] * e;
        A += g_pacc[(bh * NSPLIT + s) * DHEAD + d] * e;
    }
    const int b = bh / HEADS;
    const int h = bh % HEADS;
    g_attn[b * EDIM + h * DHEAD + d] = A / L;
}

// ---------------- launch ---------------------------------------------------
extern "C" void kernel_launch(void* const* d_in, const int* in_sizes, int n_in,
                              void* d_out, int out_size) {
    // Defensive input mapping based on element counts.
    const float *x, *kc, *vc, *Wq, *bq, *Wk, *bk, *Wv, *bv, *Wo, *bo;
    if (in_sizes[0] == BATCH * EDIM) {
        // signature/dict order: x, kc, vc, Wq, bq, Wk, bk, Wv, bv, Wo, bo
        x  = (const float*)d_in[0];
        kc = (const float*)d_in[1];
        vc = (const float*)d_in[2];
        Wq = (const float*)d_in[3];
        bq = (const float*)d_in[4];
        Wk = (const float*)d_in[5];
        bk = (const float*)d_in[6];
        Wv = (const float*)d_in[7];
        bv = (const float*)d_in[8];
        Wo = (const float*)d_in[9];
        bo = (const float*)d_in[10];
    } else {
        // alphabetical order: Wk, Wo, Wq, Wv, bk, bo, bq, bv, kc, vc, x
        Wk = (const float*)d_in[0];
        Wo = (const float*)d_in[1];
        Wq = (const float*)d_in[2];
        Wv = (const float*)d_in[3];
        bk = (const float*)d_in[4];
        bo = (const float*)d_in[5];
        bq = (const float*)d_in[6];
        bv = (const float*)d_in[7];
        kc = (const float*)d_in[8];
        vc = (const float*)d_in[9];
        x  = (const float*)d_in[10];
    }

    float* out  = (float*)d_out;                                   // [8,1,4096]
    float* kout = out + (size_t)BATCH * EDIM;                      // [8,32,2048,128]
    float* vout = kout + (size_t)BATCH * HEADS * TTOT * DHEAD;     // [8,32,2048,128]

    qkv_gemv<<<dim3(128, 3), 256>>>(x, Wq, bq, Wk, bk, Wv, bv);
    attn_kernel<<<dim3(NSPLIT, HEADS, BATCH), 256>>>(kc, vc, kout, vout);
    combine_kernel<<<BATCH * HEADS, DHEAD>>>();
    out_gemv<<<128, 256>>>(Wo, bo, out);
}